// round 2
// baseline (speedup 1.0000x reference)
#include <cuda_runtime.h>
#include <cuda_bf16.h>
#include <cstdint>

// Problem constants (fixed by the dataset)
#define K_DIM 256
#define N_DIM 64
#define MAX_NODES 100000

// Scratch for pre_sup = X @ W  (no cudaMalloc allowed)
__device__ float g_pre[(size_t)MAX_NODES * N_DIM];
// Index-dtype flag: 1 if indices are int64, 0 if int32
__device__ int g_idx64;

// ---------------------------------------------------------------------------
// Kernel 0: detect index dtype. int64 non-negative values < 2^31 have all-zero
// high words; int32 data at odd 32-bit positions holds real (mostly nonzero)
// indices. Deterministic: same inputs -> same flag.
// ---------------------------------------------------------------------------
__global__ void detect_idx_kernel(const unsigned int* __restrict__ rows_u32, int E)
{
    if (threadIdx.x == 0 && blockIdx.x == 0) {
        int n = E < 1024 ? E : 1024;
        int is64 = 1;
        for (int i = 0; i < n; i++) {
            if (rows_u32[2 * i + 1] != 0u) { is64 = 0; break; }
        }
        g_idx64 = is64;
    }
}

// ---------------------------------------------------------------------------
// Kernel 1: GEMM  pre_sup[M,64] = X[M,256] @ W[256,64]
// Block: 128 threads, tile 128(M) x 64(N), thread tile 8x8, BK=32.
// ---------------------------------------------------------------------------
#define BM 128
#define BK 32

__global__ void __launch_bounds__(128) gemm_kernel(
    const float* __restrict__ x, const float* __restrict__ w, int M)
{
    __shared__ float As[BM][BK + 1];   // [row][k], +1 pad: conflict-free column reads
    __shared__ float Bs[BK][N_DIM];    // [k][col]

    const int tid = threadIdx.x;
    const int tx  = tid & 7;    // col group: cols tx*8 .. tx*8+7
    const int ty  = tid >> 3;   // row group: rows ty*8 .. ty*8+7 (0..15)
    const int rowBase = blockIdx.x * BM;

    float acc[8][8];
#pragma unroll
    for (int i = 0; i < 8; i++)
#pragma unroll
        for (int j = 0; j < 8; j++) acc[i][j] = 0.0f;

    for (int kb = 0; kb < K_DIM; kb += BK) {
        // ---- load A tile: 128 rows x 32 k
#pragma unroll
        for (int i = 0; i < 8; i++) {
            int r   = i * 16 + (tid >> 3);
            int kk  = (tid & 7) * 4;
            int gr  = rowBase + r;
            float4 v = make_float4(0.f, 0.f, 0.f, 0.f);
            if (gr < M)
                v = *(const float4*)(x + (size_t)gr * K_DIM + kb + kk);
            As[r][kk + 0] = v.x;
            As[r][kk + 1] = v.y;
            As[r][kk + 2] = v.z;
            As[r][kk + 3] = v.w;
        }
        // ---- load B tile: 32 k x 64 cols
#pragma unroll
        for (int i = 0; i < 4; i++) {
            int idx = (i * 128 + tid) * 4;   // 0..2044 step 4
            int kk  = idx >> 6;
            int cc  = idx & 63;
            *(float4*)&Bs[kk][cc] =
                *(const float4*)(w + (size_t)(kb + kk) * N_DIM + cc);
        }
        __syncthreads();

#pragma unroll 8
        for (int k = 0; k < BK; k++) {
            float b[8], a[8];
            *(float4*)&b[0] = *(float4*)&Bs[k][tx * 8];
            *(float4*)&b[4] = *(float4*)&Bs[k][tx * 8 + 4];
#pragma unroll
            for (int i = 0; i < 8; i++) a[i] = As[ty * 8 + i][k];
#pragma unroll
            for (int i = 0; i < 8; i++)
#pragma unroll
                for (int j = 0; j < 8; j++)
                    acc[i][j] = fmaf(a[i], b[j], acc[i][j]);
        }
        __syncthreads();
    }

    // ---- store pre_sup
#pragma unroll
    for (int i = 0; i < 8; i++) {
        int gr = rowBase + ty * 8 + i;
        if (gr < M) {
            *(float4*)(g_pre + (size_t)gr * N_DIM + tx * 8)     = *(float4*)&acc[i][0];
            *(float4*)(g_pre + (size_t)gr * N_DIM + tx * 8 + 4) = *(float4*)&acc[i][4];
        }
    }
}

// ---------------------------------------------------------------------------
// Kernel 2: out[r, :] = bias[:]  (initialize before scatter-add)
// ---------------------------------------------------------------------------
__global__ void bias_init_kernel(float* __restrict__ out,
                                 const float* __restrict__ bias, int n4)
{
    int idx = blockIdx.x * blockDim.x + threadIdx.x;
    if (idx >= n4) return;
    int c4 = (idx & 15) * 4;   // column quad within the 64-wide row
    float4 b = *(const float4*)(bias + c4);
    *(float4*)(out + (size_t)idx * 4) = b;
}

// ---------------------------------------------------------------------------
// Kernel 3: scatter  out[rows[e], :] += vals[e] * pre_sup[cols[e], :]
// One thread per (edge, column-quad): 16 threads/edge, vectorized red.add.v4
// ---------------------------------------------------------------------------
__device__ __forceinline__ void red_add_v4(float* addr, float4 v)
{
    asm volatile("red.global.add.v4.f32 [%0], {%1, %2, %3, %4};"
                 :: "l"(addr), "f"(v.x), "f"(v.y), "f"(v.z), "f"(v.w)
                 : "memory");
}

__global__ void scatter_kernel(const void* __restrict__ rows_p,
                               const void* __restrict__ cols_p,
                               const float* __restrict__ vals,
                               float* __restrict__ out, int E)
{
    int idx = blockIdx.x * blockDim.x + threadIdx.x;
    int e = idx >> 4;
    if (e >= E) return;
    int q = idx & 15;

    int r, c;
    if (g_idx64) {
        r = (int)((const long long*)rows_p)[e];
        c = (int)((const long long*)cols_p)[e];
    } else {
        r = ((const int*)rows_p)[e];
        c = ((const int*)cols_p)[e];
    }
    float v = vals[e];

    float4 p = *(const float4*)(g_pre + (size_t)c * N_DIM + q * 4);
    float4 g = make_float4(p.x * v, p.y * v, p.z * v, p.w * v);
    red_add_v4(out + (size_t)r * N_DIM + q * 4, g);
}

// ---------------------------------------------------------------------------
// Kernel 4: in-place ReLU
// ---------------------------------------------------------------------------
__global__ void relu_kernel(float* __restrict__ out, int n4)
{
    int idx = blockIdx.x * blockDim.x + threadIdx.x;
    if (idx >= n4) return;
    float4 v = *(float4*)(out + (size_t)idx * 4);
    v.x = fmaxf(v.x, 0.f);
    v.y = fmaxf(v.y, 0.f);
    v.z = fmaxf(v.z, 0.f);
    v.w = fmaxf(v.w, 0.f);
    *(float4*)(out + (size_t)idx * 4) = v;
}

// ---------------------------------------------------------------------------
// Launch
// Inputs (metadata order):
//   0: x            float32 [N, 256]
//   1: support_rows int32/int64 [E]
//   2: support_cols int32/int64 [E]
//   3: support_vals float32 [E]
//   4: weight       float32 [256, 64]
//   5: bias         float32 [64]
// Output: float32 [N, 64]
// ---------------------------------------------------------------------------
extern "C" void kernel_launch(void* const* d_in, const int* in_sizes, int n_in,
                              void* d_out, int out_size)
{
    const float* x    = (const float*)d_in[0];
    const void*  rows = d_in[1];
    const void*  cols = d_in[2];
    const float* vals = (const float*)d_in[3];
    const float* w    = (const float*)d_in[4];
    const float* bias = (const float*)d_in[5];
    float*       out  = (float*)d_out;

    const int N = in_sizes[0] / K_DIM;
    const int E = in_sizes[1];
    const int n4 = N * N_DIM / 4;   // float4 count of output

    detect_idx_kernel<<<1, 32>>>((const unsigned int*)rows, E);
    gemm_kernel<<<(N + BM - 1) / BM, 128>>>(x, w, N);
    bias_init_kernel<<<(n4 + 255) / 256, 256>>>(out, bias, n4);
    scatter_kernel<<<((E * 16) + 255) / 256, 256>>>(rows, cols, vals, out, E);
    relu_kernel<<<(n4 + 255) / 256, 256>>>(out, n4);
}